// round 2
// baseline (speedup 1.0000x reference)
#include <cuda_runtime.h>
#include <math.h>

// Problem constants
#define Bn   16
#define Nn   16
#define Hh   896
#define Ww   896
#define Cc   3
#define PH   300
#define PW   300
#define MINPH 60.0f

#define NPIX (Hh*Ww)                         // 802816
#define IMG_ELEMS ((size_t)Bn*Hh*Ww*Cc)      // 38,535,168

// Output layout: imgs_out [B,H,W,C], pboxes [B,N,4], valid [B,N], td [B,N,3], grads [PH,PW,C]
#define OFF_PBOX  (IMG_ELEMS)
#define OFF_VALID (OFF_PBOX + (size_t)Bn*Nn*4)
#define OFF_TD    (OFF_VALID + (size_t)Bn*Nn)
#define OFF_GRADS (OFF_TD + (size_t)Bn*Nn*3)

// Scratch (__device__ globals; no allocations allowed)
__device__ int4   g_boxi[Bn*Nn];     // {yp, xp, ph, pw}; ph=pw=0 if invalid
__device__ float4 g_boxf[Bn*Nn];     // {inv_y, yp*inv_y+0.5, inv_x, xp*inv_x+0.5}
__device__ float  g_A[Bn*Nn*PH];     // row weight sums per box
__device__ float  g_Bw[Bn*Nn*PW];    // col weight sums per box

// ---------------------------------------------------------------------------
// Kernel 1: per-box setup (_create) + small outputs
// ---------------------------------------------------------------------------
__global__ void k_setup(const float* __restrict__ boxes,
                        const int*   __restrict__ td,
                        float* __restrict__ out)
{
    int t = threadIdx.x;
    if (t >= Bn*Nn) return;

    float ymin = boxes[t*4+0];
    float xmin = boxes[t*4+1];
    float ymax = boxes[t*4+2];
    float xmax = boxes[t*4+3];

    float h  = ymax - ymin;
    float w  = xmax - xmin;
    float pw = h * 0.5f;
    float ph = pw;
    float oy = ymin + h * 0.5f;
    float ox = xmin + w * 0.5f;
    float yp = fmaxf(oy - ph * 0.5f, 0.0f);
    float xp = fmaxf(ox - pw * 0.5f, 0.0f);
    if (yp + ph > (float)Hh) yp = (float)Hh - ph;
    if (xp + pw > (float)Ww) xp = (float)Ww - pw;

    float* out_pb = out + OFF_PBOX;
    out_pb[t*4+0] = yp; out_pb[t*4+1] = xp; out_pb[t*4+2] = ph; out_pb[t*4+3] = pw;

    bool valid = (ph > MINPH);
    out[OFF_VALID + t] = valid ? 1.0f : 0.0f;

    #pragma unroll
    for (int k = 0; k < 3; ++k)
        out[OFF_TD + (size_t)t*3 + k] = (td[t*3+k] != 0) ? 1.0f : 0.0f;

    if (!valid) {
        g_boxi[t] = make_int4(0, 0, 0, 0);
        g_boxf[t] = make_float4(0.f, 0.f, 0.f, 0.f);
    } else {
        int ypi = (int)yp;
        int xpi = (int)xp;
        int phi = max((int)ph, 1);
        int pwi = max((int)pw, 1);
        g_boxi[t] = make_int4(ypi, xpi, phi, pwi);
        float s0 = (float)phi / (float)PH;  float inv0 = 1.0f / s0;
        float s1 = (float)pwi / (float)PW;  float inv1 = 1.0f / s1;
        g_boxf[t] = make_float4(inv0, (float)ypi * inv0 + 0.5f,
                                inv1, (float)xpi * inv1 + 0.5f);
    }
}

// ---------------------------------------------------------------------------
// Kernel 2: image composite with per-tile box culling + float4 fast path.
// Tile = 128 cols x 4 rows. 128 threads: tx=t&31 -> 4-px x-chunk, ty=t>>5 -> row.
// ---------------------------------------------------------------------------
__global__ void __launch_bounds__(128) k_image(const float* __restrict__ images,
                                               const float* __restrict__ patch,
                                               float* __restrict__ out)
{
    const int b  = blockIdx.z;
    const int i0 = blockIdx.y * 4;
    const int j0 = blockIdx.x * 128;
    const int t  = threadIdx.x;

    __shared__ int4     sbi[Nn];
    __shared__ float4   sbf[Nn];
    __shared__ unsigned smask;

    if (t < 32) {
        bool inter = false;
        if (t < Nn) {
            int4 bx = g_boxi[b*Nn + t];
            sbi[t] = bx;
            sbf[t] = g_boxf[b*Nn + t];
            inter = (bx.z > 0) &&
                    (bx.x < i0 + 4)   && (bx.x + bx.z > i0) &&
                    (bx.y < j0 + 128) && (bx.y + bx.w > j0);
        }
        unsigned m = __ballot_sync(0xffffffffu, inter);
        if (t == 0) smask = m;
    }
    __syncthreads();

    const int tx = t & 31;
    const int ty = t >> 5;
    const int i  = i0 + ty;
    const int j  = j0 + tx * 4;

    size_t base = ((size_t)b * NPIX + (size_t)i * Ww + j) * 3;   // float index, 16B aligned
    float4*       dst = (float4*)(out + base);
    const float4* src = (const float4*)(images + base);

    unsigned mask = smask;
    if (mask == 0u) {
        // fast path: pure vectorized copy
        dst[0] = src[0];
        dst[1] = src[1];
        dst[2] = src[2];
        return;
    }

    float v[12];
    #pragma unroll
    for (int k = 0; k < 4; ++k) {
        int jj = j + k;
        int hit = -1;
        unsigned m = mask;
        while (m) {
            int n = 31 - __clz(m);        // highest set bit first (last box wins)
            int4 bx = sbi[n];
            if ((unsigned)(i - bx.x) < (unsigned)bx.z &&
                (unsigned)(jj - bx.y) < (unsigned)bx.w) { hit = n; break; }
            m &= ~(1u << n);
        }
        if (hit < 0) {
            v[k*3+0] = images[base + k*3 + 0];
            v[k*3+1] = images[base + k*3 + 1];
            v[k*3+2] = images[base + k*3 + 2];
        } else {
            float4 f = sbf[hit];
            float u  = ((float)i  + 0.5f) * f.x - f.y;    // interior (scale<1)
            float vv = ((float)jj + 0.5f) * f.z - f.w;
            float fu = floorf(u), fv = floorf(vv);
            float du = u - fu,    dv = vv - fv;
            int r0 = (int)fu, c0 = (int)fv;
            const float* p00 = patch + ((size_t)r0 * PW + c0) * 3;
            float w00 = (1.0f-du)*(1.0f-dv);
            float w01 = (1.0f-du)*dv;
            float w10 = du*(1.0f-dv);
            float w11 = du*dv;
            #pragma unroll
            for (int c = 0; c < 3; ++c)
                v[k*3+c] = w00*p00[c] + w01*p00[3+c] + w10*p00[PW*3+c] + w11*p00[PW*3+3+c];
        }
    }
    dst[0] = make_float4(v[0], v[1], v[2],  v[3]);
    dst[1] = make_float4(v[4], v[5], v[6],  v[7]);
    dst[2] = make_float4(v[8], v[9], v[10], v[11]);
}

// ---------------------------------------------------------------------------
// Kernel 3: per-box separable VJP vectors A (rows) and B (cols).
// ---------------------------------------------------------------------------
__global__ void k_ab()
{
    int bn = blockIdx.x;
    int p  = threadIdx.x;
    if (p >= PH) return;
    int4   bx = g_boxi[bn];
    float4 f  = g_boxf[bn];
    float a = 0.0f, bb = 0.0f;
    if (bx.z > 0) {
        {
            float r = (float)bx.z / (float)PH;
            float inv = f.x;
            int k0 = (int)floorf(((float)p + 0.5f) * r - 0.5f) - 2;
            #pragma unroll
            for (int dk = 0; dk < 5; ++dk) {
                int k = k0 + dk;
                if (k < 0 || k >= bx.z) continue;
                float u = ((float)k + 0.5f) * inv - 0.5f;
                float wgt = 1.0f - fabsf(u - (float)p);
                if (wgt > 0.0f) a += wgt;
            }
        }
        {
            float r = (float)bx.w / (float)PW;
            float inv = f.z;
            int k0 = (int)floorf(((float)p + 0.5f) * r - 0.5f) - 2;
            #pragma unroll
            for (int dk = 0; dk < 5; ++dk) {
                int k = k0 + dk;
                if (k < 0 || k >= bx.w) continue;
                float u = ((float)k + 0.5f) * inv - 0.5f;
                float wgt = 1.0f - fabsf(u - (float)p);
                if (wgt > 0.0f) bb += wgt;
            }
        }
    }
    g_A [bn*PH + p] = a;
    g_Bw[bn*PW + p] = bb;
}

// ---------------------------------------------------------------------------
// Kernel 4: grads[p,q,c] = sum_b ( sum_n A_bn[p]*B_bn[q] ) * hg[b,p,q,c]
// One block per row p; thread = column q. A staged in smem (broadcast),
// B read coalesced (L2-resident), hg streamed once.
// ---------------------------------------------------------------------------
__global__ void __launch_bounds__(320) k_grads(const float* __restrict__ hg,
                                               float* __restrict__ outg)
{
    const int p = blockIdx.x;
    const int q = threadIdx.x;

    __shared__ float As[Bn*Nn];
    for (int idx = threadIdx.x; idx < Bn*Nn; idx += blockDim.x)
        As[idx] = g_A[idx*PH + p];
    __syncthreads();
    if (q >= PW) return;

    float s[Bn];
    #pragma unroll
    for (int b = 0; b < Bn; ++b) s[b] = 0.0f;

    #pragma unroll 8
    for (int bn = 0; bn < Bn*Nn; ++bn)
        s[bn >> 4] += As[bn] * g_Bw[bn*PW + q];

    float o0 = 0.f, o1 = 0.f, o2 = 0.f;
    #pragma unroll
    for (int b = 0; b < Bn; ++b) {
        size_t hb = (((size_t)b * PH + p) * PW + q) * 3;
        o0 += s[b] * __ldg(hg + hb + 0);
        o1 += s[b] * __ldg(hg + hb + 1);
        o2 += s[b] * __ldg(hg + hb + 2);
    }
    size_t gb = ((size_t)p * PW + q) * 3;
    outg[gb+0] = o0;
    outg[gb+1] = o1;
    outg[gb+2] = o2;
}

// ---------------------------------------------------------------------------
extern "C" void kernel_launch(void* const* d_in, const int* in_sizes, int n_in,
                              void* d_out, int out_size)
{
    const float* boxes  = (const float*)d_in[0];
    const float* images = (const float*)d_in[1];
    const float* patch  = (const float*)d_in[2];
    const float* hg     = (const float*)d_in[3];
    const int*   td     = (const int*)  d_in[4];
    float* out = (float*)d_out;

    k_setup<<<1, 256>>>(boxes, td, out);
    k_ab<<<Bn*Nn, 320>>>();
    k_image<<<dim3(Ww/128, Hh/4, Bn), 128>>>(images, patch, out);
    k_grads<<<PH, 320>>>(hg, out + OFF_GRADS);
}

// round 3
// speedup vs baseline: 1.2283x; 1.2283x over previous
#include <cuda_runtime.h>
#include <math.h>

// Problem constants
#define Bn   16
#define Nn   16
#define Hh   896
#define Ww   896
#define Cc   3
#define PH   300
#define PW   300
#define MINPH 60.0f

#define NPIX (Hh*Ww)                         // 802816
#define IMG_ELEMS ((size_t)Bn*Hh*Ww*Cc)      // 38,535,168

// Output layout: imgs_out [B,H,W,C], pboxes [B,N,4], valid [B,N], td [B,N,3], grads [PH,PW,C]
#define OFF_PBOX  (IMG_ELEMS)
#define OFF_VALID (OFF_PBOX + (size_t)Bn*Nn*4)
#define OFF_TD    (OFF_VALID + (size_t)Bn*Nn)
#define OFF_GRADS (OFF_TD + (size_t)Bn*Nn*3)

// Scratch (__device__ globals; no allocations allowed)
__device__ int4   g_boxi[Bn*Nn];       // {yp, xp, ph, pw}; ph=pw=0 if invalid
__device__ float4 g_boxf[Bn*Nn];       // {inv_y, yp*inv_y+0.5, inv_x, xp*inv_x+0.5}
__device__ float  g_A[Bn*Nn*PH];       // row weight sums per box
__device__ float  g_Bw[Bn*Nn*PW];      // col weight sums per box
__device__ float  g_S[(size_t)Bn*PH*PW]; // per-image rank-16 weight field (5.76 MB)

// ---------------------------------------------------------------------------
// Kernel 1: per-box setup (_create) + small outputs
// ---------------------------------------------------------------------------
__global__ void k_setup(const float* __restrict__ boxes,
                        const int*   __restrict__ td,
                        float* __restrict__ out)
{
    int t = threadIdx.x;
    if (t >= Bn*Nn) return;

    float ymin = boxes[t*4+0];
    float xmin = boxes[t*4+1];
    float ymax = boxes[t*4+2];
    float xmax = boxes[t*4+3];

    float h  = ymax - ymin;
    float w  = xmax - xmin;
    float pw = h * 0.5f;
    float ph = pw;
    float oy = ymin + h * 0.5f;
    float ox = xmin + w * 0.5f;
    float yp = fmaxf(oy - ph * 0.5f, 0.0f);
    float xp = fmaxf(ox - pw * 0.5f, 0.0f);
    if (yp + ph > (float)Hh) yp = (float)Hh - ph;
    if (xp + pw > (float)Ww) xp = (float)Ww - pw;

    float* out_pb = out + OFF_PBOX;
    out_pb[t*4+0] = yp; out_pb[t*4+1] = xp; out_pb[t*4+2] = ph; out_pb[t*4+3] = pw;

    bool valid = (ph > MINPH);
    out[OFF_VALID + t] = valid ? 1.0f : 0.0f;

    #pragma unroll
    for (int k = 0; k < 3; ++k)
        out[OFF_TD + (size_t)t*3 + k] = (td[t*3+k] != 0) ? 1.0f : 0.0f;

    if (!valid) {
        g_boxi[t] = make_int4(0, 0, 0, 0);
        g_boxf[t] = make_float4(0.f, 0.f, 0.f, 0.f);
    } else {
        int ypi = (int)yp;
        int xpi = (int)xp;
        int phi = max((int)ph, 1);
        int pwi = max((int)pw, 1);
        g_boxi[t] = make_int4(ypi, xpi, phi, pwi);
        float s0 = (float)phi / (float)PH;  float inv0 = 1.0f / s0;
        float s1 = (float)pwi / (float)PW;  float inv1 = 1.0f / s1;
        g_boxf[t] = make_float4(inv0, (float)ypi * inv0 + 0.5f,
                                inv1, (float)xpi * inv1 + 0.5f);
    }
}

// ---------------------------------------------------------------------------
// Kernel 2: per-box separable VJP vectors A (rows) and B (cols).
// ---------------------------------------------------------------------------
__global__ void k_ab()
{
    int bn = blockIdx.x;
    int p  = threadIdx.x;
    if (p >= PH) return;
    int4   bx = g_boxi[bn];
    float4 f  = g_boxf[bn];
    float a = 0.0f, bb = 0.0f;
    if (bx.z > 0) {
        {
            float r = (float)bx.z / (float)PH;
            float inv = f.x;
            int k0 = (int)floorf(((float)p + 0.5f) * r - 0.5f) - 2;
            #pragma unroll
            for (int dk = 0; dk < 5; ++dk) {
                int k = k0 + dk;
                if (k < 0 || k >= bx.z) continue;
                float u = ((float)k + 0.5f) * inv - 0.5f;
                float wgt = 1.0f - fabsf(u - (float)p);
                if (wgt > 0.0f) a += wgt;
            }
        }
        {
            float r = (float)bx.w / (float)PW;
            float inv = f.z;
            int k0 = (int)floorf(((float)p + 0.5f) * r - 0.5f) - 2;
            #pragma unroll
            for (int dk = 0; dk < 5; ++dk) {
                int k = k0 + dk;
                if (k < 0 || k >= bx.w) continue;
                float u = ((float)k + 0.5f) * inv - 0.5f;
                float wgt = 1.0f - fabsf(u - (float)p);
                if (wgt > 0.0f) bb += wgt;
            }
        }
    }
    g_A [bn*PH + p] = a;
    g_Bw[bn*PW + p] = bb;
}

// ---------------------------------------------------------------------------
// Kernel 3: S[b][p][q] = sum_n A_bn[p] * B_bn[q]  (rank-16 outer product)
// grid = (p-chunks of 30, b). A_b rows staged in smem (broadcast reads),
// B_bn[q] held in 16 registers per thread. Coalesced stores.
// ---------------------------------------------------------------------------
#define PCHUNK 30
__global__ void __launch_bounds__(320) k_s()
{
    const int b  = blockIdx.y;
    const int p0 = blockIdx.x * PCHUNK;
    const int q  = threadIdx.x;

    __shared__ float As[Nn][PH];
    for (int idx = threadIdx.x; idx < Nn*PH; idx += 320) {
        int n = idx / PH, p = idx - n * PH;
        As[n][p] = g_A[(b*Nn + n)*PH + p];
    }
    __syncthreads();
    if (q >= PW) return;

    float Br[Nn];
    #pragma unroll
    for (int n = 0; n < Nn; ++n)
        Br[n] = g_Bw[(b*Nn + n)*PW + q];

    #pragma unroll
    for (int dp = 0; dp < PCHUNK; ++dp) {
        int p = p0 + dp;
        float s = 0.0f;
        #pragma unroll
        for (int n = 0; n < Nn; ++n)
            s += As[n][p] * Br[n];
        g_S[((size_t)b*PH + p)*PW + q] = s;
    }
}

// ---------------------------------------------------------------------------
// Kernel 4: grads[p,q,c] = sum_b S[b,p,q] * hg[b,p,q,c] (pure streaming)
// ---------------------------------------------------------------------------
__global__ void __launch_bounds__(256) k_g(const float* __restrict__ hg,
                                           float* __restrict__ outg)
{
    int idx = blockIdx.x * 256 + threadIdx.x;     // idx = p*PW + q
    if (idx >= PH*PW) return;

    float o0 = 0.f, o1 = 0.f, o2 = 0.f;
    #pragma unroll
    for (int b = 0; b < Bn; ++b) {
        float  s  = g_S[(size_t)b*PH*PW + idx];
        size_t hb = ((size_t)b*PH*PW + idx) * 3;
        o0 += s * hg[hb+0];
        o1 += s * hg[hb+1];
        o2 += s * hg[hb+2];
    }
    size_t gb = (size_t)idx * 3;
    outg[gb+0] = o0;
    outg[gb+1] = o1;
    outg[gb+2] = o2;
}

// ---------------------------------------------------------------------------
// Kernel 5: image composite. Tile 128x4, 128 threads; each thread owns a
// 4-px group. Group-level hit resolution: the first (highest-n) box covering
// ANY of the 4 px is the top box for every pixel it covers; if it covers ALL,
// hit is uniform (no image read needed). Misses are float4 copies. Only
// box-edge groups fall back to per-pixel search.
// ---------------------------------------------------------------------------
__global__ void __launch_bounds__(128) k_image(const float* __restrict__ images,
                                               const float* __restrict__ patch,
                                               float* __restrict__ out)
{
    const int b  = blockIdx.z;
    const int i0 = blockIdx.y * 4;
    const int j0 = blockIdx.x * 128;
    const int t  = threadIdx.x;

    __shared__ int4     sbi[Nn];
    __shared__ float4   sbf[Nn];
    __shared__ unsigned smask;

    if (t < 32) {
        bool inter = false;
        if (t < Nn) {
            int4 bx = g_boxi[b*Nn + t];
            sbi[t] = bx;
            sbf[t] = g_boxf[b*Nn + t];
            inter = (bx.z > 0) &&
                    (bx.x < i0 + 4)   && (bx.x + bx.z > i0) &&
                    (bx.y < j0 + 128) && (bx.y + bx.w > j0);
        }
        unsigned m = __ballot_sync(0xffffffffu, inter);
        if (t == 0) smask = m;
    }
    __syncthreads();

    const int i = i0 + (t >> 5);
    const int j = j0 + (t & 31) * 4;

    size_t base = ((size_t)b * NPIX + (size_t)i * Ww + j) * 3;   // 16B aligned
    float4*       dst = (float4*)(out + base);
    const float4* src = (const float4*)(images + base);

    // group-level search over the box stack (top box first)
    int  hitg = -1;
    bool uni  = false;
    unsigned m = smask;
    while (m) {
        int n = 31 - __clz(m);
        int4 bx = sbi[n];
        if ((unsigned)(i - bx.x) < (unsigned)bx.z &&
            (j + 3 >= bx.y) && (j < bx.y + bx.w)) {
            hitg = n;
            uni  = (j >= bx.y) && (j + 3 < bx.y + bx.w);
            break;
        }
        m &= ~(1u << n);
    }

    if (hitg < 0) {
        // pure copy
        dst[0] = src[0];
        dst[1] = src[1];
        dst[2] = src[2];
        return;
    }

    if (uni) {
        // uniform bilinear for all 4 px; row weights shared
        float4 f = sbf[hitg];
        float u  = ((float)i + 0.5f) * f.x - f.y;
        float fu = floorf(u);
        float du = u - fu;
        int   r0 = (int)fu;
        const float* prow = patch + (size_t)r0 * PW * 3;
        float v[12];
        #pragma unroll
        for (int k = 0; k < 4; ++k) {
            float vv = ((float)(j + k) + 0.5f) * f.z - f.w;
            float fv = floorf(vv);
            float dv = vv - fv;
            int   c0 = (int)fv;
            const float* p00 = prow + (size_t)c0 * 3;
            float w00 = (1.0f-du)*(1.0f-dv);
            float w01 = (1.0f-du)*dv;
            float w10 = du*(1.0f-dv);
            float w11 = du*dv;
            #pragma unroll
            for (int c = 0; c < 3; ++c)
                v[k*3+c] = w00*p00[c] + w01*p00[3+c] + w10*p00[PW*3+c] + w11*p00[PW*3+3+c];
        }
        dst[0] = make_float4(v[0], v[1], v[2],  v[3]);
        dst[1] = make_float4(v[4], v[5], v[6],  v[7]);
        dst[2] = make_float4(v[8], v[9], v[10], v[11]);
        return;
    }

    // mixed group (box edge): per-pixel resolution, boxes above hitg excluded
    float4 s0 = src[0], s1 = src[1], s2 = src[2];
    float v[12] = { s0.x, s0.y, s0.z, s0.w, s1.x, s1.y, s1.z, s1.w,
                    s2.x, s2.y, s2.z, s2.w };
    unsigned mask_le = smask & (unsigned)((2ull << hitg) - 1ull);
    #pragma unroll
    for (int k = 0; k < 4; ++k) {
        int jj = j + k;
        int hit = -1;
        unsigned mm = mask_le;
        while (mm) {
            int n = 31 - __clz(mm);
            int4 bx = sbi[n];
            if ((unsigned)(i  - bx.x) < (unsigned)bx.z &&
                (unsigned)(jj - bx.y) < (unsigned)bx.w) { hit = n; break; }
            mm &= ~(1u << n);
        }
        if (hit >= 0) {
            float4 f = sbf[hit];
            float u  = ((float)i  + 0.5f) * f.x - f.y;
            float vv = ((float)jj + 0.5f) * f.z - f.w;
            float fu = floorf(u), fv = floorf(vv);
            float du = u - fu,    dv = vv - fv;
            int r0 = (int)fu, c0 = (int)fv;
            const float* p00 = patch + ((size_t)r0 * PW + c0) * 3;
            float w00 = (1.0f-du)*(1.0f-dv);
            float w01 = (1.0f-du)*dv;
            float w10 = du*(1.0f-dv);
            float w11 = du*dv;
            #pragma unroll
            for (int c = 0; c < 3; ++c)
                v[k*3+c] = w00*p00[c] + w01*p00[3+c] + w10*p00[PW*3+c] + w11*p00[PW*3+3+c];
        }
    }
    dst[0] = make_float4(v[0], v[1], v[2],  v[3]);
    dst[1] = make_float4(v[4], v[5], v[6],  v[7]);
    dst[2] = make_float4(v[8], v[9], v[10], v[11]);
}

// ---------------------------------------------------------------------------
extern "C" void kernel_launch(void* const* d_in, const int* in_sizes, int n_in,
                              void* d_out, int out_size)
{
    const float* boxes  = (const float*)d_in[0];
    const float* images = (const float*)d_in[1];
    const float* patch  = (const float*)d_in[2];
    const float* hg     = (const float*)d_in[3];
    const int*   td     = (const int*)  d_in[4];
    float* out = (float*)d_out;

    k_setup<<<1, 256>>>(boxes, td, out);
    k_ab<<<Bn*Nn, 320>>>();
    k_s<<<dim3(PH/PCHUNK, Bn), 320>>>();
    k_g<<<(PH*PW + 255)/256, 256>>>(hg, out + OFF_GRADS);
    k_image<<<dim3(Ww/128, Hh/4, Bn), 128>>>(images, patch, out);
}

// round 4
// speedup vs baseline: 1.3927x; 1.1338x over previous
#include <cuda_runtime.h>
#include <math.h>

// Problem constants
#define Bn   16
#define Nn   16
#define Hh   896
#define Ww   896
#define Cc   3
#define PH   300
#define PW   300
#define MINPH 60.0f

#define NPIX (Hh*Ww)                         // 802816
#define IMG_ELEMS ((size_t)Bn*Hh*Ww*Cc)      // 38,535,168

// Output layout: imgs_out [B,H,W,C], pboxes [B,N,4], valid [B,N], td [B,N,3], grads [PH,PW,C]
#define OFF_PBOX  (IMG_ELEMS)
#define OFF_VALID (OFF_PBOX + (size_t)Bn*Nn*4)
#define OFF_TD    (OFF_VALID + (size_t)Bn*Nn)
#define OFF_GRADS (OFF_TD + (size_t)Bn*Nn*3)

// Scratch (__device__ globals)
__device__ int4   g_boxi[Bn*Nn];     // {yp, xp, ph, pw}; ph=pw=0 if invalid
__device__ float4 g_boxf[Bn*Nn];     // {inv_y, yp*inv_y+0.5, inv_x, xp*inv_x+0.5}
__device__ float  g_A[Bn*Nn*PH];     // row weight sums per box
__device__ float  g_Bw[Bn*Nn*PW];    // col weight sums per box

// ---------------------------------------------------------------------------
// Kernel 1: fused _create (thread 0) + separable VJP vectors A/B (all threads).
// One block per (b,n).
// ---------------------------------------------------------------------------
__global__ void __launch_bounds__(320) k_init(const float* __restrict__ boxes,
                                              const int*   __restrict__ td,
                                              float* __restrict__ out)
{
    const int bn = blockIdx.x;
    __shared__ int4   sbi;
    __shared__ float4 sbf;

    if (threadIdx.x == 0) {
        float ymin = boxes[bn*4+0];
        float xmin = boxes[bn*4+1];
        float ymax = boxes[bn*4+2];
        float xmax = boxes[bn*4+3];

        float h  = ymax - ymin;
        float w  = xmax - xmin;
        float pw = h * 0.5f;
        float ph = pw;
        float oy = ymin + h * 0.5f;
        float ox = xmin + w * 0.5f;
        float yp = fmaxf(oy - ph * 0.5f, 0.0f);
        float xp = fmaxf(ox - pw * 0.5f, 0.0f);
        if (yp + ph > (float)Hh) yp = (float)Hh - ph;
        if (xp + pw > (float)Ww) xp = (float)Ww - pw;

        float* out_pb = out + OFF_PBOX;
        out_pb[bn*4+0] = yp; out_pb[bn*4+1] = xp;
        out_pb[bn*4+2] = ph; out_pb[bn*4+3] = pw;

        bool valid = (ph > MINPH);
        out[OFF_VALID + bn] = valid ? 1.0f : 0.0f;
        #pragma unroll
        for (int k = 0; k < 3; ++k)
            out[OFF_TD + (size_t)bn*3 + k] = (td[bn*3+k] != 0) ? 1.0f : 0.0f;

        int4 bi; float4 bf;
        if (!valid) {
            bi = make_int4(0,0,0,0);
            bf = make_float4(0.f,0.f,0.f,0.f);
        } else {
            int ypi = (int)yp, xpi = (int)xp;
            int phi = max((int)ph, 1);
            int pwi = max((int)pw, 1);
            bi = make_int4(ypi, xpi, phi, pwi);
            float s0 = (float)phi / (float)PH;  float inv0 = 1.0f / s0;
            float s1 = (float)pwi / (float)PW;  float inv1 = 1.0f / s1;
            bf = make_float4(inv0, (float)ypi*inv0 + 0.5f,
                             inv1, (float)xpi*inv1 + 0.5f);
        }
        g_boxi[bn] = bi;  g_boxf[bn] = bf;
        sbi = bi;  sbf = bf;
    }
    __syncthreads();

    int p = threadIdx.x;
    if (p >= PH) return;
    int4   bx = sbi;
    float4 f  = sbf;
    float a = 0.0f, bb = 0.0f;
    if (bx.z > 0) {
        {
            float r = (float)bx.z / (float)PH;
            int k0 = (int)floorf(((float)p + 0.5f) * r - 0.5f) - 2;
            #pragma unroll
            for (int dk = 0; dk < 5; ++dk) {
                int k = k0 + dk;
                if (k < 0 || k >= bx.z) continue;
                float u = ((float)k + 0.5f) * f.x - 0.5f;
                float wgt = 1.0f - fabsf(u - (float)p);
                if (wgt > 0.0f) a += wgt;
            }
        }
        {
            float r = (float)bx.w / (float)PW;
            int k0 = (int)floorf(((float)p + 0.5f) * r - 0.5f) - 2;
            #pragma unroll
            for (int dk = 0; dk < 5; ++dk) {
                int k = k0 + dk;
                if (k < 0 || k >= bx.w) continue;
                float u = ((float)k + 0.5f) * f.z - 0.5f;
                float wgt = 1.0f - fabsf(u - (float)p);
                if (wgt > 0.0f) bb += wgt;
            }
        }
    }
    g_A [bn*PH + p] = a;
    g_Bw[bn*PW + p] = bb;
}

// ---------------------------------------------------------------------------
// Bilinear sample of patch (3 channels) at image pixel (fi, jj) under box f.
// ---------------------------------------------------------------------------
__device__ __forceinline__ void bil3(float4 f, float fi, int jj,
                                     const float* __restrict__ patch, float* o)
{
    float u  = fi * f.x - f.y;
    float vv = ((float)jj + 0.5f) * f.z - f.w;
    float fu = floorf(u), fv = floorf(vv);
    float du = u - fu,    dv = vv - fv;
    int r0 = (int)fu, c0 = (int)fv;
    const float* p00 = patch + ((size_t)r0 * PW + c0) * 3;
    float w00 = (1.0f-du)*(1.0f-dv);
    float w01 = (1.0f-du)*dv;
    float w10 = du*(1.0f-dv);
    float w11 = du*dv;
    #pragma unroll
    for (int c = 0; c < 3; ++c)
        o[c] = w00*p00[c] + w01*p00[3+c] + w10*p00[PW*3+c] + w11*p00[PW*3+3+c];
}

// ---------------------------------------------------------------------------
// Kernel 2: image composite. One warp per 128-px row segment; lane l owns
// float4 indices l, l+32, l+64 of the 384-float segment (fully coalesced).
// Warp-level box mask (row containment included). Each float4 spans exactly
// 2 pixels; bilinear computed per covered pixel; src4 loaded only when some
// element is uncovered.
// ---------------------------------------------------------------------------
__global__ void __launch_bounds__(256) k_image(const float* __restrict__ images,
                                               const float* __restrict__ patch,
                                               float* __restrict__ out)
{
    const int b    = blockIdx.z;
    const int j0   = blockIdx.x * 128;
    const int i    = blockIdx.y * 8 + (threadIdx.x >> 5);
    const int lane = threadIdx.x & 31;

    __shared__ int4   sbi[Nn];
    __shared__ float4 sbf[Nn];
    if (threadIdx.x < Nn) {
        sbi[threadIdx.x] = g_boxi[b*Nn + threadIdx.x];
        sbf[threadIdx.x] = g_boxf[b*Nn + threadIdx.x];
    }
    __syncthreads();

    bool inter = false;
    if (lane < Nn) {
        int4 bx = sbi[lane];
        inter = (bx.z > 0) &&
                ((unsigned)(i - bx.x) < (unsigned)bx.z) &&   // row containment
                (bx.y < j0 + 128) && (bx.y + bx.w > j0);     // col overlap
    }
    unsigned mask = __ballot_sync(0xffffffffu, inter);

    size_t fbase = ((size_t)b * NPIX + (size_t)i * Ww + j0) * 3;  // 16B aligned
    const float4* src4 = (const float4*)(images + fbase);
    float4*       dst4 = (float4*)(out + fbase);

    if (mask == 0u) {
        dst4[lane     ] = src4[lane     ];
        dst4[lane + 32] = src4[lane + 32];
        dst4[lane + 64] = src4[lane + 64];
        return;
    }

    const float fi = (float)i + 0.5f;

    #pragma unroll
    for (int r = 0; r < 3; ++r) {
        int l4 = lane + r*32;
        int f0 = l4 * 4;               // local float index of element 0
        int pa = f0 / 3;               // first pixel spanned
        int pb = (f0 + 3) / 3;         // second pixel spanned (pa+1 typically)

        // topmost covering box per pixel (mask boxes already contain row i)
        int hitA = -1, hitB = -1;
        {
            int ja = j0 + pa, jb = j0 + pb;
            unsigned m = mask;
            while (m) {
                int n = 31 - __clz(m);
                int4 bx = sbi[n];
                if (hitA < 0 && (unsigned)(ja - bx.y) < (unsigned)bx.w) hitA = n;
                if (hitB < 0 && (unsigned)(jb - bx.y) < (unsigned)bx.w) hitB = n;
                if (hitA >= 0 && hitB >= 0) break;
                m &= ~(1u << n);
            }
        }

        float va[3], vb[3];
        if (hitA >= 0) bil3(sbf[hitA], fi, j0 + pa, patch, va);
        if (hitB >= 0) bil3(sbf[hitB], fi, j0 + pb, patch, vb);

        float4 v = make_float4(0.f, 0.f, 0.f, 0.f);
        if (hitA < 0 || hitB < 0)
            v = src4[l4];              // only needed if some element uncovered

        float ov[4] = { v.x, v.y, v.z, v.w };
        #pragma unroll
        for (int e = 0; e < 4; ++e) {
            int fidx = f0 + e;
            int p = fidx / 3;
            int c = fidx - p * 3;
            if (p == pa) { if (hitA >= 0) ov[e] = va[c]; }
            else         { if (hitB >= 0) ov[e] = vb[c]; }
        }
        dst4[l4] = make_float4(ov[0], ov[1], ov[2], ov[3]);
    }
}

// ---------------------------------------------------------------------------
// Kernel 3 (fused): grads[p,q,c] = sum_b (sum_n A_bn[p]*B_bn[q]) * hg[b,p,q,c]
// Block covers 256 consecutive (p,q) -> at most 2 distinct p; A staged in smem.
// B rows are L2/L1-resident (307 KB total); hg streamed once.
// ---------------------------------------------------------------------------
__global__ void __launch_bounds__(256) k_grads(const float* __restrict__ hg,
                                               float* __restrict__ outg)
{
    const int base = blockIdx.x * 256;
    const int idx  = base + threadIdx.x;     // p*PW + q
    const int p0   = base / PW;

    __shared__ float As[2][Bn*Nn];
    {
        int t = threadIdx.x;                  // 256 == Bn*Nn
        As[0][t] = g_A[t*PH + p0];
        As[1][t] = (p0 + 1 < PH) ? g_A[t*PH + p0 + 1] : 0.0f;
    }
    __syncthreads();
    if (idx >= PH*PW) return;

    const int p = idx / PW;
    const int q = idx - p * PW;
    const float* Arow = As[p - p0];

    float o0 = 0.f, o1 = 0.f, o2 = 0.f;
    #pragma unroll 4
    for (int b = 0; b < Bn; ++b) {
        float s = 0.f;
        #pragma unroll
        for (int n = 0; n < Nn; ++n)
            s += Arow[b*Nn + n] * g_Bw[(b*Nn + n)*PW + q];
        size_t hb = ((size_t)b * PH * PW + idx) * 3;
        o0 += s * hg[hb+0];
        o1 += s * hg[hb+1];
        o2 += s * hg[hb+2];
    }
    size_t gb = (size_t)idx * 3;
    outg[gb+0] = o0;
    outg[gb+1] = o1;
    outg[gb+2] = o2;
}

// ---------------------------------------------------------------------------
extern "C" void kernel_launch(void* const* d_in, const int* in_sizes, int n_in,
                              void* d_out, int out_size)
{
    const float* boxes  = (const float*)d_in[0];
    const float* images = (const float*)d_in[1];
    const float* patch  = (const float*)d_in[2];
    const float* hg     = (const float*)d_in[3];
    const int*   td     = (const int*)  d_in[4];
    float* out = (float*)d_out;

    k_init<<<Bn*Nn, 320>>>(boxes, td, out);
    k_image<<<dim3(Ww/128, Hh/8, Bn), 256>>>(images, patch, out);
    k_grads<<<(PH*PW + 255)/256, 256>>>(hg, out + OFF_GRADS);
}